// round 6
// baseline (speedup 1.0000x reference)
#include <cuda_runtime.h>
#include <cstdint>

// Problem constants
#define BB   2
#define SS   2048
#define DD   1024
#define HH   16
#define DKK  64
#define MROWS (BB*SS)   // 4096

// ---------------------------------------------------------------------------
// Scratch (static device globals — allocation rules forbid cudaMalloc)
// ---------------------------------------------------------------------------
__device__ float g_Q[MROWS * DD];
__device__ float g_K[MROWS * DD];
__device__ float g_V[MROWS * DD];

// ---------------------------------------------------------------------------
// Helpers
// ---------------------------------------------------------------------------
__device__ __forceinline__ uint32_t f2tf(float f) {
    uint32_t u;
    asm("cvt.rna.tf32.f32 %0, %1;" : "=r"(u) : "f"(f));
    return u;
}

__device__ __forceinline__ void mma_tf32(float c[4], const uint32_t a[4], const uint32_t b[2]) {
    asm volatile(
        "mma.sync.aligned.m16n8k8.row.col.f32.tf32.tf32.f32 "
        "{%0,%1,%2,%3}, {%4,%5,%6,%7}, {%8,%9}, {%0,%1,%2,%3};"
        : "+f"(c[0]), "+f"(c[1]), "+f"(c[2]), "+f"(c[3])
        : "r"(a[0]), "r"(a[1]), "r"(a[2]), "r"(a[3]),
          "r"(b[0]), "r"(b[1]));
}

__device__ __forceinline__ void cp16(uint32_t dst, const void* src) {
    asm volatile("cp.async.cg.shared.global [%0], [%1], 16;" :: "r"(dst), "l"(src));
}
__device__ __forceinline__ void cp_commit() {
    asm volatile("cp.async.commit_group;" ::: "memory");
}
__device__ __forceinline__ void cp_wait0() {
    asm volatile("cp.async.wait_group 0;" ::: "memory");
}
__device__ __forceinline__ void cp_wait1() {
    asm volatile("cp.async.wait_group 1;" ::: "memory");
}

// ---------------------------------------------------------------------------
// Projection GEMM: Y = X @ W^T + bias
// CTA tile 128x128, BK=16, 128 threads = 4 warps (2x2), warp tile 64x64.
// 3-stage cp.async pipeline, one __syncthreads per k-step, raw floats staged,
// cvt.rna applied at fragment load (numerics identical to converting at STS).
// ---------------------------------------------------------------------------
#define PM 128
#define PN 128
#define PK 16
#define PSTR 20
#define PSTAGES 3
#define PSTW (2 * PM * PSTR)                 // words per stage (A + B)
#define PROJ_DYN_BYTES (PSTAGES * PSTW * 4)  // 61440

__global__ __launch_bounds__(128) void proj_kernel(
    const float* __restrict__ X,
    const float* __restrict__ W0, const float* __restrict__ bv0,
    const float* __restrict__ W1, const float* __restrict__ bv1,
    const float* __restrict__ W2, const float* __restrict__ bv2)
{
    extern __shared__ float psm[];
    const uint32_t smb = (uint32_t)__cvta_generic_to_shared(psm);

    const int z = blockIdx.z;
    const float* __restrict__ Wp = (z == 0) ? W0 : (z == 1) ? W1 : W2;
    const float* __restrict__ bp = (z == 0) ? bv0 : (z == 1) ? bv1 : bv2;
    float* __restrict__ Yp       = (z == 0) ? g_Q : (z == 1) ? g_K : g_V;

    const int bm = blockIdx.y * PM;
    const int bn = blockIdx.x * PN;

    const int t    = threadIdx.x;
    const int w    = t >> 5;
    const int lane = t & 31;
    const int g    = lane >> 2;
    const int tig  = lane & 3;
    const int wm   = (w >> 1) * 64;
    const int wn   = (w & 1)  * 64;

    // cp.async mapping: id = t + 128*i (i<4) -> row = id/4, col4 = (id%4)*4
    const int lrow = t >> 2;
    const int lkq  = (t & 3) * 4;

    auto issue = [&](int kt) {
        const int s  = kt % PSTAGES;
        const int kb = kt * PK;
        #pragma unroll
        for (int i = 0; i < 4; i++) {
            int r = lrow + i * 32;
            cp16(smb + (uint32_t)((s * PSTW + r * PSTR + lkq) * 4),
                 &X[(size_t)(bm + r) * DD + kb + lkq]);
            cp16(smb + (uint32_t)((s * PSTW + PM * PSTR + r * PSTR + lkq) * 4),
                 &Wp[(size_t)(bn + r) * DD + kb + lkq]);
        }
        cp_commit();
    };

    float acc[4][8][4];
    #pragma unroll
    for (int i = 0; i < 4; i++)
        #pragma unroll
        for (int j = 0; j < 8; j++)
            #pragma unroll
            for (int e = 0; e < 4; e++) acc[i][j][e] = 0.f;

    const int KT = DD / PK;  // 64
    issue(0);
    issue(1);

    for (int kt = 0; kt < KT; kt++) {
        if (kt + 1 < KT) cp_wait1(); else cp_wait0();
        __syncthreads();                       // publish stage kt; frees buf (kt+2)%3
        if (kt + 2 < KT) issue(kt + 2);

        const float* As = psm + (kt % PSTAGES) * PSTW;
        const float* Bs = As + PM * PSTR;

        #pragma unroll
        for (int ks = 0; ks < 2; ks++) {
            const int k0 = ks * 8;
            uint32_t af[4][4], bf[8][2];
            #pragma unroll
            for (int i = 0; i < 4; i++) {
                int m0 = wm + i * 16;
                af[i][0] = f2tf(As[(m0 + g)     * PSTR + k0 + tig]);
                af[i][1] = f2tf(As[(m0 + g + 8) * PSTR + k0 + tig]);
                af[i][2] = f2tf(As[(m0 + g)     * PSTR + k0 + tig + 4]);
                af[i][3] = f2tf(As[(m0 + g + 8) * PSTR + k0 + tig + 4]);
            }
            #pragma unroll
            for (int j = 0; j < 8; j++) {
                int n0 = wn + j * 8;
                bf[j][0] = f2tf(Bs[(n0 + g) * PSTR + k0 + tig]);
                bf[j][1] = f2tf(Bs[(n0 + g) * PSTR + k0 + tig + 4]);
            }
            #pragma unroll
            for (int i = 0; i < 4; i++)
                #pragma unroll
                for (int j = 0; j < 8; j++)
                    mma_tf32(acc[i][j], af[i], bf[j]);
        }
    }

    // epilogue: add bias, write Y
    #pragma unroll
    for (int j = 0; j < 8; j++) {
        const int n0 = bn + wn + j * 8 + 2 * tig;
        const float b0 = bp[n0], b1 = bp[n0 + 1];
        #pragma unroll
        for (int i = 0; i < 4; i++) {
            const int m0 = bm + wm + i * 16;
            *(float2*)&Yp[(size_t)(m0 + g)     * DD + n0] =
                make_float2(acc[i][j][0] + b0, acc[i][j][1] + b1);
            *(float2*)&Yp[(size_t)(m0 + g + 8) * DD + n0] =
                make_float2(acc[i][j][2] + b0, acc[i][j][3] + b1);
        }
    }
}

// ---------------------------------------------------------------------------
// Causal flash attention, v4: cp.async double-buffered K/V, ONE __syncthreads
// per KV tile. CTA: 128 threads = 4 warps, Q tile 64 rows (warp owns 16).
// Smem 104KB -> 2 independent CTAs/SM (automatic phase stagger per SMSP).
// Q staged once (tf32, pre-scaled). K/V staged raw; cvt.rna at frag load
// (numerics identical to previous rounds).
// ---------------------------------------------------------------------------
#define QSTR 68
#define KSTR 68
#define VSTR 72
// word layout: Qs(u32)[64*QSTR] | K(float)[2][64*KSTR] | V(float)[2][64*VSTR] | P(u32)[64*KSTR]
#define AW_Q 0
#define AW_K (64*QSTR)
#define AW_V (AW_K + 2*64*KSTR)
#define AW_P (AW_V + 2*64*VSTR)
#define ATTN_DYN_WORDS (AW_P + 64*KSTR)
#define ATTN_DYN_BYTES (ATTN_DYN_WORDS * 4)   // 106496

__global__ __launch_bounds__(128) void attn_kernel(float* __restrict__ out)
{
    extern __shared__ uint32_t dyn[];
    uint32_t*    Qs  = dyn + AW_Q;
    float*       Kst = (float*)(dyn + AW_K);
    float*       Vst = (float*)(dyn + AW_V);
    uint32_t*    Pu  = dyn + AW_P;
    const uint32_t smb = (uint32_t)__cvta_generic_to_shared(dyn);

    const int qtile = gridDim.x - 1 - (int)blockIdx.x;  // 0..31, heavy first
    const int bh    = blockIdx.y;
    const int b     = bh >> 4;
    const int h     = bh & 15;
    const int browQ = b * SS + qtile * 64;
    const int hc    = h * DKK;

    const int t    = threadIdx.x;
    const int w    = t >> 5;
    const int lane = t & 31;
    const int g    = lane >> 2;
    const int tig  = lane & 3;
    const int qr   = w * 16;   // warp's q-row base in the 64-row tile

    // cp.async issue for KV stage j -> buffer j&1 (8+8 chunks of 16B per thread)
    auto issue_kv = [&](int j) {
        const int kvbase = b * SS + j * 64;
        const int buf    = j & 1;
        #pragma unroll
        for (int i = 0; i < 8; i++) {
            int id = t + 128 * i;
            int r  = id >> 4;
            int c4 = (id & 15) * 4;
            cp16(smb + (uint32_t)((AW_K + buf * 64 * KSTR + r * KSTR + c4) * 4),
                 &g_K[(size_t)(kvbase + r) * DD + hc + c4]);
            cp16(smb + (uint32_t)((AW_V + buf * 64 * VSTR + r * VSTR + c4) * 4),
                 &g_V[(size_t)(kvbase + r) * DD + hc + c4]);
        }
        cp_commit();
    };

    // stage Q tile once (pre-scaled by 1/sqrt(64), tf32)
    #pragma unroll
    for (int i = 0; i < 8; i++) {
        int id = t + 128 * i;
        int r  = id >> 4;
        int c4 = (id & 15) * 4;
        float4 q4 = *(const float4*)&g_Q[(size_t)(browQ + r) * DD + hc + c4];
        *(uint4*)&Qs[r * QSTR + c4] = make_uint4(
            f2tf(q4.x * 0.125f), f2tf(q4.y * 0.125f),
            f2tf(q4.z * 0.125f), f2tf(q4.w * 0.125f));
    }

    issue_kv(0);

    uint32_t* Ps = &Pu[qr * KSTR];  // warp-private P slice (16 rows)

    float o[8][4];
    #pragma unroll
    for (int d = 0; d < 8; d++)
        #pragma unroll
        for (int e = 0; e < 4; e++) o[d][e] = 0.f;
    float mprev0 = -1e30f, mprev1 = -1e30f;
    float l0 = 0.f, l1 = 0.f;

    const int jend = qtile;
    for (int j = 0; j <= jend; j++) {
        const float* Ks = Kst + (j & 1) * 64 * KSTR;
        const float* Vs = Vst + (j & 1) * 64 * VSTR;

        cp_wait0();          // stage j landed (committed last iteration)
        __syncthreads();     // publish stage j; all warps done with buf (j+1)&1
        if (j + 1 <= jend) issue_kv(j + 1);

        // S = Q K^T (K converted to tf32 at frag load)
        float s[8][4];
        #pragma unroll
        for (int n = 0; n < 8; n++) { s[n][0] = s[n][1] = s[n][2] = s[n][3] = 0.f; }

        #pragma unroll
        for (int kk = 0; kk < 8; kk++) {
            uint32_t af[4];
            af[0] = Qs[(qr + g)     * QSTR + kk * 8 + tig];
            af[1] = Qs[(qr + g + 8) * QSTR + kk * 8 + tig];
            af[2] = Qs[(qr + g)     * QSTR + kk * 8 + tig + 4];
            af[3] = Qs[(qr + g + 8) * QSTR + kk * 8 + tig + 4];
            #pragma unroll
            for (int n = 0; n < 8; n++) {
                uint32_t bf[2];
                bf[0] = f2tf(Ks[(n * 8 + g) * KSTR + kk * 8 + tig]);
                bf[1] = f2tf(Ks[(n * 8 + g) * KSTR + kk * 8 + tig + 4]);
                mma_tf32(s[n], af, bf);
            }
        }

        // causal mask (diagonal tile only)
        if (j == jend) {
            const int r0 = qr + g, r1 = r0 + 8;
            #pragma unroll
            for (int n = 0; n < 8; n++) {
                const int c = n * 8 + 2 * tig;
                if (c     > r0) s[n][0] = -1e30f;
                if (c + 1 > r0) s[n][1] = -1e30f;
                if (c     > r1) s[n][2] = -1e30f;
                if (c + 1 > r1) s[n][3] = -1e30f;
            }
        }

        // online softmax
        float mt0 = -1e30f, mt1 = -1e30f;
        #pragma unroll
        for (int n = 0; n < 8; n++) {
            mt0 = fmaxf(mt0, fmaxf(s[n][0], s[n][1]));
            mt1 = fmaxf(mt1, fmaxf(s[n][2], s[n][3]));
        }
        mt0 = fmaxf(mt0, __shfl_xor_sync(0xffffffffu, mt0, 1));
        mt0 = fmaxf(mt0, __shfl_xor_sync(0xffffffffu, mt0, 2));
        mt1 = fmaxf(mt1, __shfl_xor_sync(0xffffffffu, mt1, 1));
        mt1 = fmaxf(mt1, __shfl_xor_sync(0xffffffffu, mt1, 2));

        const float mnew0  = fmaxf(mprev0, mt0);
        const float mnew1  = fmaxf(mprev1, mt1);
        const float alpha0 = __expf(mprev0 - mnew0);
        const float alpha1 = __expf(mprev1 - mnew1);
        mprev0 = mnew0;
        mprev1 = mnew1;

        float rs0 = 0.f, rs1 = 0.f;
        #pragma unroll
        for (int n = 0; n < 8; n++) {
            float p0 = __expf(s[n][0] - mnew0);
            float p1 = __expf(s[n][1] - mnew0);
            float p2 = __expf(s[n][2] - mnew1);
            float p3 = __expf(s[n][3] - mnew1);
            rs0 += p0 + p1;
            rs1 += p2 + p3;
            *(uint2*)&Ps[g       * KSTR + n * 8 + 2 * tig] = make_uint2(f2tf(p0), f2tf(p1));
            *(uint2*)&Ps[(g + 8) * KSTR + n * 8 + 2 * tig] = make_uint2(f2tf(p2), f2tf(p3));
        }
        rs0 += __shfl_xor_sync(0xffffffffu, rs0, 1);
        rs0 += __shfl_xor_sync(0xffffffffu, rs0, 2);
        rs1 += __shfl_xor_sync(0xffffffffu, rs1, 1);
        rs1 += __shfl_xor_sync(0xffffffffu, rs1, 2);
        l0 = l0 * alpha0 + rs0;
        l1 = l1 * alpha1 + rs1;

        #pragma unroll
        for (int d = 0; d < 8; d++) {
            o[d][0] *= alpha0; o[d][1] *= alpha0;
            o[d][2] *= alpha1; o[d][3] *= alpha1;
        }

        __syncwarp();  // warp-private P stores visible to this warp's loads

        // O += P V (V converted to tf32 at frag load)
        #pragma unroll
        for (int kk = 0; kk < 8; kk++) {
            uint32_t af[4];
            af[0] = Ps[g       * KSTR + kk * 8 + tig];
            af[1] = Ps[(g + 8) * KSTR + kk * 8 + tig];
            af[2] = Ps[g       * KSTR + kk * 8 + tig + 4];
            af[3] = Ps[(g + 8) * KSTR + kk * 8 + tig + 4];
            #pragma unroll
            for (int d = 0; d < 8; d++) {
                uint32_t bf[2];
                bf[0] = f2tf(Vs[(kk * 8 + tig)     * VSTR + d * 8 + g]);
                bf[1] = f2tf(Vs[(kk * 8 + tig + 4) * VSTR + d * 8 + g]);
                mma_tf32(o[d], af, bf);
            }
        }
    }

    // normalize and write output
    const float inv0 = 1.f / l0;
    const float inv1 = 1.f / l1;
    float* O0 = out + (size_t)(browQ + qr + g) * DD + hc;
    float* O1 = O0 + 8 * DD;
    #pragma unroll
    for (int d = 0; d < 8; d++) {
        *(float2*)&O0[d * 8 + 2 * tig] = make_float2(o[d][0] * inv0, o[d][1] * inv0);
        *(float2*)&O1[d * 8 + 2 * tig] = make_float2(o[d][2] * inv1, o[d][3] * inv1);
    }
}

// ---------------------------------------------------------------------------
// Launch
// ---------------------------------------------------------------------------
extern "C" void kernel_launch(void* const* d_in, const int* in_sizes, int n_in,
                              void* d_out, int out_size)
{
    const float* x  = (const float*)d_in[0];
    const float* Wq = (const float*)d_in[1];
    const float* bq = (const float*)d_in[2];
    const float* Wk = (const float*)d_in[3];
    const float* bk = (const float*)d_in[4];
    const float* Wv = (const float*)d_in[5];
    const float* bv = (const float*)d_in[6];
    float* out = (float*)d_out;

    cudaFuncSetAttribute(proj_kernel,
                         cudaFuncAttributeMaxDynamicSharedMemorySize,
                         PROJ_DYN_BYTES);
    cudaFuncSetAttribute(attn_kernel,
                         cudaFuncAttributeMaxDynamicSharedMemorySize,
                         ATTN_DYN_BYTES);

    proj_kernel<<<dim3(DD / PN, MROWS / PM, 3), 128, PROJ_DYN_BYTES>>>(
        x, Wq, bq, Wk, bk, Wv, bv);
    attn_kernel<<<dim3(SS / 64, BB * HH), 128, ATTN_DYN_BYTES>>>(out);
}